// round 15
// baseline (speedup 1.0000x reference)
#include <cuda_runtime.h>
#include <cuda_fp16.h>
#include <cstdint>

// ---------------- problem constants ----------------
#define D_ 2048
#define B_ 4
#define T_ 2048
#define M_ (B_*T_)          // 8192

#define MD ((size_t)M_*(size_t)D_)   // 16,777,216
#define DD ((size_t)D_*(size_t)D_)   //  4,194,304  (4*DD == MD)

#define NCH 32
#define CL  (T_/NCH)                 // 64
#define BDN (B_*NCH*D_)              // 262,144

// ---------------- scratch (static device globals — allocation-free) --------
__device__ __align__(256) __half g_xh[3*MD];    // mixed activations (fp16)
__device__ __align__(256) __half g_wh[4*DD];    // weights (fp16)
__device__ __align__(256) float  g_kvr[2*MD];   // k, v (fp32 GEMM outputs)
__device__ __align__(256) __half g_sr[MD];      // sigmoid(r) (fp16, GEMM epilogue)
__device__ __align__(256) __half g_uh[MD];      // wkv*sigmoid(r) (fp16)
__device__ __align__(256) float  g_agg[3*BDN];  // chunk aggregates
__device__ __align__(256) float  g_car[3*BDN];  // chunk carry-ins

// ---------------- fused prep: weight->fp16 AND time-shift mix ----------------
__global__ void prep_kernel(const float* __restrict__ x,
                            const float* __restrict__ mk,
                            const float* __restrict__ mv,
                            const float* __restrict__ mr,
                            const float* __restrict__ W0, const float* __restrict__ W1,
                            const float* __restrict__ W2, const float* __restrict__ W3)
{
    size_t i = (size_t)blockIdx.x * blockDim.x + threadIdx.x;
    if (i >= MD) return;

    size_t which = i / DD;
    const float* Ws = (which == 0) ? W0 : (which == 1) ? W1 : (which == 2) ? W2 : W3;
    g_wh[i] = __float2half(Ws[i - which*DD]);

    int d = (int)(i & (size_t)(D_-1));
    int t = (int)((i / D_) & (size_t)(T_-1));
    float xv = x[i];
    float lx = (t > 0) ? x[i - D_] : 0.0f;
    float dx = xv - lx;

    g_xh[i]        = __float2half(fmaf(dx, mk[d], lx));
    g_xh[MD + i]   = __float2half(fmaf(dx, mv[d], lx));
    g_xh[2*MD + i] = __float2half(fmaf(dx, mr[d], lx));
}

// ---------------- fp16 single-pass GEMM (R10 inner loop, z-fused) -----------
// If z == sigZ, the epilogue applies sigmoid and stores fp16 into Hsig
// instead of fp32 into C (used for the r-projection).
#define BM 128
#define BN 128
#define BK 64
#define NSTG 3
#define TILE_ELEMS (BM*BK)           // 8192 fp16
#define STAGE_ELEMS (2*TILE_ELEMS)
#define STAGE_BYTES (STAGE_ELEMS*2)  // 32768

__device__ __forceinline__ uint32_t cvta_s(const void* p) {
    return (uint32_t)__cvta_generic_to_shared(p);
}
__device__ __forceinline__ void cp16(uint32_t s, const void* g) {
    asm volatile("cp.async.cg.shared.global [%0], [%1], 16;\n" :: "r"(s), "l"(g));
}
__device__ __forceinline__ uint32_t swoff64(int r, int c) {
    return (uint32_t)(r*128 + ((c ^ (r & 7)) << 4));
}

#define MMA_FP16(cc, aa, bb)                                                    \
    asm volatile("mma.sync.aligned.m16n8k16.row.col.f32.f16.f16.f32 "            \
                 "{%0,%1,%2,%3},{%4,%5,%6,%7},{%8,%9},{%0,%1,%2,%3};\n"          \
                 : "+f"(cc[0]), "+f"(cc[1]), "+f"(cc[2]), "+f"(cc[3])            \
                 : "r"(aa[0]), "r"(aa[1]), "r"(aa[2]), "r"(aa[3]),               \
                   "r"(bb[0]), "r"(bb[1]))

#define LDSM4(dst, ad)                                                           \
    asm volatile("ldmatrix.sync.aligned.m8n8.x4.shared.b16 {%0,%1,%2,%3},[%4];\n"\
                 : "=r"((dst)[0]), "=r"((dst)[1]), "=r"((dst)[2]), "=r"((dst)[3])\
                 : "r"(ad))

__global__ void __launch_bounds__(256, 2)
gemm_kernel(const __half* __restrict__ Abase, const __half* __restrict__ Bbase,
            float* __restrict__ Cbase, __half* __restrict__ Hsig,
            int M, int N, int K, int strideAz, int strideBz, int sigZ)
{
    extern __shared__ __align__(16) char smem_raw[];
    const uint32_t sbase = cvta_s(smem_raw);

    const int tid  = threadIdx.x;
    const int lane = tid & 31;
    const int warp = tid >> 5;
    const int wm   = warp >> 2;
    const int wn   = warp & 3;

    const int z  = blockIdx.z;
    const __half* Ah = Abase + (size_t)z * (size_t)strideAz;
    const __half* Bh = Bbase + (size_t)z * (size_t)strideBz;
    float*        C  = Cbase + (size_t)z * (size_t)strideAz;

    const int bm = blockIdx.y * BM;
    const int bn = blockIdx.x * BN;

    float c[4][4][4];
    #pragma unroll
    for (int i = 0; i < 4; i++)
        #pragma unroll
        for (int j = 0; j < 4; j++)
            #pragma unroll
            for (int q = 0; q < 4; q++) c[i][j][q] = 0.0f;

    const __half* gbase[2] = { Ah + (size_t)bm*K, Bh + (size_t)bn*K };

    const int rA = wm*64 + (lane & 15);
    const int rB = wn*32 + (lane & 15);
    const int hi = lane >> 4;
    uint32_t aAddr0 = sbase + (uint32_t)(rA*128);
    uint32_t bAddr0 = sbase + (uint32_t)(TILE_ELEMS*2 + rB*128);
    uint32_t chA[4], chB[4];
    #pragma unroll
    for (int kk = 0; kk < 4; kk++) {
        chA[kk] = (uint32_t)(((kk*2 + hi) ^ (rA & 7)) << 4);
        chB[kk] = (uint32_t)(((kk*2 + hi) ^ (rB & 7)) << 4);
    }

    auto issue_loads = [&](int s, int bi) {
        const int k0 = s * BK;
        const uint32_t st = sbase + (uint32_t)bi * STAGE_BYTES;
        #pragma unroll
        for (int q = 0; q < 8; q++) {
            int cid = tid + q*256;
            int op  = cid >> 10;
            int wi  = cid & 1023;
            int rr  = wi >> 3, cc = wi & 7;
            cp16(st + (uint32_t)op*(TILE_ELEMS*2) + swoff64(rr, cc),
                 gbase[op] + (size_t)rr*K + k0 + cc*8);
        }
        asm volatile("cp.async.commit_group;\n");
    };

    auto compute_stage = [&](int bi) {
        const uint32_t so = (uint32_t)bi * STAGE_BYTES;
        const uint32_t aB = aAddr0 + so;
        const uint32_t bB = bAddr0 + so;

        uint32_t af[2][4][4];
        uint32_t bf[2][4][2];

        {
            uint32_t t0[4], t1[4];
            LDSM4(t0, bB + chB[0]);
            LDSM4(t1, bB + 2048 + chB[0]);
            bf[0][0][0]=t0[0]; bf[0][0][1]=t0[2];
            bf[0][1][0]=t0[1]; bf[0][1][1]=t0[3];
            bf[0][2][0]=t1[0]; bf[0][2][1]=t1[2];
            bf[0][3][0]=t1[1]; bf[0][3][1]=t1[3];
            #pragma unroll
            for (int mt = 0; mt < 4; mt++)
                LDSM4(af[0][mt], aB + (uint32_t)(mt*2048) + chA[0]);
        }

        #pragma unroll
        for (int kk = 0; kk < 4; kk++) {
            const int cb = kk & 1;
            if (kk < 3) {
                uint32_t t0[4], t1[4];
                LDSM4(t0, bB + chB[kk+1]);
                LDSM4(t1, bB + 2048 + chB[kk+1]);
                bf[cb^1][0][0]=t0[0]; bf[cb^1][0][1]=t0[2];
                bf[cb^1][1][0]=t0[1]; bf[cb^1][1][1]=t0[3];
                bf[cb^1][2][0]=t1[0]; bf[cb^1][2][1]=t1[2];
                bf[cb^1][3][0]=t1[1]; bf[cb^1][3][1]=t1[3];
                #pragma unroll
                for (int mt = 0; mt < 4; mt++)
                    LDSM4(af[cb^1][mt], aB + (uint32_t)(mt*2048) + chA[kk+1]);
            }
            #pragma unroll
            for (int mt = 0; mt < 4; mt++)
                #pragma unroll
                for (int nt = 0; nt < 4; nt++)
                    MMA_FP16(c[mt][nt], af[cb][mt], bf[cb][nt]);
        }
    };

    const int NS = K / BK;
    issue_loads(0, 0);
    issue_loads(1, 1);

    for (int s = 0; s < NS; s++) {
        const int bi = s % NSTG;
        if (s + 1 < NS) asm volatile("cp.async.wait_group 1;\n" ::: "memory");
        else            asm volatile("cp.async.wait_group 0;\n" ::: "memory");
        __syncthreads();
        if (s + 2 < NS) issue_loads(s + 2, (s + 2) % NSTG);
        compute_stage(bi);
    }

    // epilogue
    if (z == sigZ) {
        // sigmoid + fp16 store (r-projection)
        #pragma unroll
        for (int mt = 0; mt < 4; mt++) {
            #pragma unroll
            for (int nt = 0; nt < 4; nt++) {
                int row = bm + wm*64 + mt*16 + (lane >> 2);
                int col = bn + wn*32 + nt*8 + (lane & 3)*2;
                #pragma unroll
                for (int h = 0; h < 2; h++) {
                    float s0 = __fdividef(1.0f, 1.0f + __expf(-c[mt][nt][2*h]));
                    float s1 = __fdividef(1.0f, 1.0f + __expf(-c[mt][nt][2*h+1]));
                    *reinterpret_cast<__half2*>(Hsig + (size_t)(row + 8*h)*N + col) =
                        __floats2half2_rn(s0, s1);
                }
            }
        }
    } else {
        #pragma unroll
        for (int mt = 0; mt < 4; mt++) {
            #pragma unroll
            for (int nt = 0; nt < 4; nt++) {
                int row = bm + wm*64 + mt*16 + (lane >> 2);
                int col = bn + wn*32 + nt*8 + (lane & 3)*2;
                *reinterpret_cast<float2*>(C + (size_t)row*N + col) =
                    make_float2(c[mt][nt][0], c[mt][nt][1]);
                *reinterpret_cast<float2*>(C + (size_t)(row+8)*N + col) =
                    make_float2(c[mt][nt][2], c[mt][nt][3]);
            }
        }
    }
}

// ============================================================================
// WKV parallel scan (single-exp forms, bit-identical to two-exp).
// ============================================================================

__global__ void wkv_chunk_kernel(const float* __restrict__ kk, const float* __restrict__ vv,
                                 const float* __restrict__ td)
{
    int g  = blockIdx.x * 256 + threadIdx.x;
    int d  = g & (D_-1);
    int ch = (g >> 11) & (NCH-1);
    int b  = g >> 16;
    float w = expf(td[d]);

    float alpha = 0.0f, beta = 0.0f, eps = -1e30f;
    size_t base = ((size_t)b * T_ + (size_t)ch * CL) * D_ + d;

    #pragma unroll 4
    for (int i = 0; i < CL; i++) {
        size_t idx = base + (size_t)i * D_;
        float kt = kk[idx];
        float vt = vv[idx];
        float ww2 = eps - w;
        float d2  = ww2 - kt;
        float e   = __expf(-fabsf(d2));
        float e1b = (d2 < 0.0f) ? e    : 1.0f;
        float e2b = (d2 < 0.0f) ? 1.0f : e;
        alpha = e1b*alpha + e2b*vt;
        beta  = e1b*beta + e2b;
        eps   = fmaxf(ww2, kt);
    }
    size_t o = ((size_t)b * NCH + ch) * D_ + d;
    g_agg[o]         = alpha;
    g_agg[BDN + o]   = beta;
    g_agg[2*BDN + o] = eps;
}

// stitch: loads batched 8 chunks ahead (MLP 24) before the dependent combine.
__global__ void wkv_stitch_kernel(const float* __restrict__ td)
{
    int g = blockIdx.x * 256 + threadIdx.x;
    int d = g & (D_-1);
    int b = g >> 11;
    float w  = expf(td[d]);
    float dl = -w * (float)CL;

    float a = 0.0f, bt = 0.0f, e = -1e30f;
    for (int c0 = 0; c0 < NCH; c0 += 8) {
        float pa[8], pb[8], pe[8];
        #pragma unroll
        for (int j = 0; j < 8; j++) {
            size_t o = ((size_t)b * NCH + c0 + j) * D_ + d;
            pa[j] = g_agg[o];
            pb[j] = g_agg[BDN + o];
            pe[j] = g_agg[2*BDN + o];
        }
        #pragma unroll
        for (int j = 0; j < 8; j++) {
            size_t o = ((size_t)b * NCH + c0 + j) * D_ + d;
            g_car[o]         = a;
            g_car[BDN + o]   = bt;
            g_car[2*BDN + o] = e;
            float ein = e + dl;
            float dd  = ein - pe[j];
            float ee  = __expf(-fabsf(dd));
            float f1  = (dd < 0.0f) ? ee   : 1.0f;
            float f2  = (dd < 0.0f) ? 1.0f : ee;
            a  = f1*a  + f2*pa[j];
            bt = f1*bt + f2*pb[j];
            e  = fmaxf(ein, pe[j]);
        }
    }
}

__global__ void wkv_apply_kernel(const float* __restrict__ kk, const float* __restrict__ vv,
                                 const float* __restrict__ td, const float* __restrict__ tf)
{
    int g  = blockIdx.x * 256 + threadIdx.x;
    int d  = g & (D_-1);
    int ch = (g >> 11) & (NCH-1);
    int b  = g >> 16;
    float w = expf(td[d]);
    float u = tf[d];

    size_t o = ((size_t)b * NCH + ch) * D_ + d;
    float alpha = g_car[o];
    float beta  = g_car[BDN + o];
    float eps   = g_car[2*BDN + o];

    size_t base = ((size_t)b * T_ + (size_t)ch * CL) * D_ + d;

    #pragma unroll 4
    for (int i = 0; i < CL; i++) {
        size_t idx = base + (size_t)i * D_;
        float kt = kk[idx];
        float vt = vv[idx];
        float sr = __half2float(g_sr[idx]);   // sigmoid(r) precomputed in GEMM

        float ww = u + kt;
        float dd = eps - ww;
        float eo = __expf(-fabsf(dd));
        float e1 = (dd < 0.0f) ? eo   : 1.0f;
        float e2 = (dd < 0.0f) ? 1.0f : eo;
        float out = __fdividef(e1*alpha + e2*vt, e1*beta + e2);

        float ww2 = eps - w;
        float d2  = ww2 - kt;
        float eb  = __expf(-fabsf(d2));
        float e1b = (d2 < 0.0f) ? eb   : 1.0f;
        float e2b = (d2 < 0.0f) ? 1.0f : eb;
        alpha = e1b*alpha + e2b*vt;
        beta  = e1b*beta + e2b;
        eps   = fmaxf(ww2, kt);

        g_uh[idx] = __float2half(out * sr);
    }
}

// ---------------- launch ----------------
extern "C" void kernel_launch(void* const* d_in, const int* in_sizes, int n_in,
                              void* d_out, int out_size)
{
    const float* x  = (const float*)d_in[0];
    const float* td = (const float*)d_in[1];
    const float* tf = (const float*)d_in[2];
    const float* mk = (const float*)d_in[3];
    const float* mv = (const float*)d_in[4];
    const float* mr = (const float*)d_in[5];
    const float* Wk = (const float*)d_in[6];
    const float* Wv = (const float*)d_in[7];
    const float* Wr = (const float*)d_in[8];
    const float* Wo = (const float*)d_in[9];
    float* out = (float*)d_out;

    __half *xh, *wh, *uh, *sr;
    float* kvr;
    cudaGetSymbolAddress((void**)&xh,  g_xh);
    cudaGetSymbolAddress((void**)&wh,  g_wh);
    cudaGetSymbolAddress((void**)&kvr, g_kvr);
    cudaGetSymbolAddress((void**)&uh,  g_uh);
    cudaGetSymbolAddress((void**)&sr,  g_sr);

    const int GEMM_SMEM = NSTG * STAGE_BYTES;  // 98304
    cudaFuncSetAttribute(gemm_kernel, cudaFuncAttributeMaxDynamicSharedMemorySize, GEMM_SMEM);

    prep_kernel<<<(unsigned)((MD + 255) / 256), 256>>>(x, mk, mv, mr, Wk, Wv, Wr, Wo);

    // fused k/v/r GEMMs: z=0,1 -> fp32 kvr; z=2 -> sigmoid -> fp16 g_sr
    dim3 grid3(D_ / BN, M_ / BM, 3);
    gemm_kernel<<<grid3, 256, GEMM_SMEM>>>(xh, wh, kvr, sr, M_, D_, D_,
                                           (int)MD, (int)DD, 2);

    wkv_chunk_kernel<<<BDN/256, 256>>>(kvr, kvr + MD, td);
    wkv_stitch_kernel<<<(B_*D_)/256, 256>>>(td);
    wkv_apply_kernel<<<BDN/256, 256>>>(kvr, kvr + MD, td, tf);

    dim3 grid1(D_ / BN, M_ / BM, 1);
    gemm_kernel<<<grid1, 256, GEMM_SMEM>>>(uh, wh + 3*DD, out, nullptr,
                                           M_, D_, D_, 0, 0, -1);
}

// round 16
// speedup vs baseline: 1.0233x; 1.0233x over previous
#include <cuda_runtime.h>
#include <cuda_fp16.h>
#include <cstdint>

// ---------------- problem constants ----------------
#define D_ 2048
#define B_ 4
#define T_ 2048
#define M_ (B_*T_)          // 8192

#define MD ((size_t)M_*(size_t)D_)   // 16,777,216
#define DD ((size_t)D_*(size_t)D_)   //  4,194,304  (4*DD == MD)

#define NCH 32
#define CL  (T_/NCH)                 // 64
#define BDN (B_*NCH*D_)              // 262,144

// ---------------- scratch (static device globals — allocation-free) --------
__device__ __align__(256) __half g_xh[3*MD];    // mixed activations (fp16)
__device__ __align__(256) __half g_wh[4*DD];    // weights (fp16)
__device__ __align__(256) float  g_kvr[3*MD];   // k, v, r (fp32 GEMM outputs)
__device__ __align__(256) __half g_uh[MD];      // wkv*sigmoid(r) (fp16)
__device__ __align__(256) float  g_agg[3*BDN];  // chunk aggregates
__device__ __align__(256) float  g_car[3*BDN];  // chunk carry-ins

// ---------------- fused prep: weight->fp16 AND time-shift mix ----------------
__global__ void prep_kernel(const float* __restrict__ x,
                            const float* __restrict__ mk,
                            const float* __restrict__ mv,
                            const float* __restrict__ mr,
                            const float* __restrict__ W0, const float* __restrict__ W1,
                            const float* __restrict__ W2, const float* __restrict__ W3)
{
    size_t i = (size_t)blockIdx.x * blockDim.x + threadIdx.x;
    if (i >= MD) return;

    size_t which = i / DD;
    const float* Ws = (which == 0) ? W0 : (which == 1) ? W1 : (which == 2) ? W2 : W3;
    g_wh[i] = __float2half(Ws[i - which*DD]);

    int d = (int)(i & (size_t)(D_-1));
    int t = (int)((i / D_) & (size_t)(T_-1));
    float xv = x[i];
    float lx = (t > 0) ? x[i - D_] : 0.0f;
    float dx = xv - lx;

    g_xh[i]        = __float2half(fmaf(dx, mk[d], lx));
    g_xh[MD + i]   = __float2half(fmaf(dx, mv[d], lx));
    g_xh[2*MD + i] = __float2half(fmaf(dx, mr[d], lx));
}

// ---------------- fp16 single-pass GEMM (R10 inner loop, z-fused) -----------
#define BM 128
#define BN 128
#define BK 64
#define NSTG 3
#define TILE_ELEMS (BM*BK)           // 8192 fp16
#define STAGE_ELEMS (2*TILE_ELEMS)
#define STAGE_BYTES (STAGE_ELEMS*2)  // 32768

__device__ __forceinline__ uint32_t cvta_s(const void* p) {
    return (uint32_t)__cvta_generic_to_shared(p);
}
__device__ __forceinline__ void cp16(uint32_t s, const void* g) {
    asm volatile("cp.async.cg.shared.global [%0], [%1], 16;\n" :: "r"(s), "l"(g));
}
__device__ __forceinline__ uint32_t swoff64(int r, int c) {
    return (uint32_t)(r*128 + ((c ^ (r & 7)) << 4));
}

#define MMA_FP16(cc, aa, bb)                                                    \
    asm volatile("mma.sync.aligned.m16n8k16.row.col.f32.f16.f16.f32 "            \
                 "{%0,%1,%2,%3},{%4,%5,%6,%7},{%8,%9},{%0,%1,%2,%3};\n"          \
                 : "+f"(cc[0]), "+f"(cc[1]), "+f"(cc[2]), "+f"(cc[3])            \
                 : "r"(aa[0]), "r"(aa[1]), "r"(aa[2]), "r"(aa[3]),               \
                   "r"(bb[0]), "r"(bb[1]))

#define LDSM4(dst, ad)                                                           \
    asm volatile("ldmatrix.sync.aligned.m8n8.x4.shared.b16 {%0,%1,%2,%3},[%4];\n"\
                 : "=r"((dst)[0]), "=r"((dst)[1]), "=r"((dst)[2]), "=r"((dst)[3])\
                 : "r"(ad))

__global__ void __launch_bounds__(256, 2)
gemm_kernel(const __half* __restrict__ Abase, const __half* __restrict__ Bbase,
            float* __restrict__ Cbase, int M, int N, int K,
            int strideAz, int strideBz)
{
    extern __shared__ __align__(16) char smem_raw[];
    const uint32_t sbase = cvta_s(smem_raw);

    const int tid  = threadIdx.x;
    const int lane = tid & 31;
    const int warp = tid >> 5;
    const int wm   = warp >> 2;
    const int wn   = warp & 3;

    const int z  = blockIdx.z;
    const __half* Ah = Abase + (size_t)z * (size_t)strideAz;
    const __half* Bh = Bbase + (size_t)z * (size_t)strideBz;
    float*        C  = Cbase + (size_t)z * (size_t)strideAz;

    const int bm = blockIdx.y * BM;
    const int bn = blockIdx.x * BN;

    float c[4][4][4];
    #pragma unroll
    for (int i = 0; i < 4; i++)
        #pragma unroll
        for (int j = 0; j < 4; j++)
            #pragma unroll
            for (int q = 0; q < 4; q++) c[i][j][q] = 0.0f;

    const __half* gbase[2] = { Ah + (size_t)bm*K, Bh + (size_t)bn*K };

    const int rA = wm*64 + (lane & 15);
    const int rB = wn*32 + (lane & 15);
    const int hi = lane >> 4;
    uint32_t aAddr0 = sbase + (uint32_t)(rA*128);
    uint32_t bAddr0 = sbase + (uint32_t)(TILE_ELEMS*2 + rB*128);
    uint32_t chA[4], chB[4];
    #pragma unroll
    for (int kk = 0; kk < 4; kk++) {
        chA[kk] = (uint32_t)(((kk*2 + hi) ^ (rA & 7)) << 4);
        chB[kk] = (uint32_t)(((kk*2 + hi) ^ (rB & 7)) << 4);
    }

    auto issue_loads = [&](int s, int bi) {
        const int k0 = s * BK;
        const uint32_t st = sbase + (uint32_t)bi * STAGE_BYTES;
        #pragma unroll
        for (int q = 0; q < 8; q++) {
            int cid = tid + q*256;
            int op  = cid >> 10;
            int wi  = cid & 1023;
            int rr  = wi >> 3, cc = wi & 7;
            cp16(st + (uint32_t)op*(TILE_ELEMS*2) + swoff64(rr, cc),
                 gbase[op] + (size_t)rr*K + k0 + cc*8);
        }
        asm volatile("cp.async.commit_group;\n");
    };

    auto compute_stage = [&](int bi) {
        const uint32_t so = (uint32_t)bi * STAGE_BYTES;
        const uint32_t aB = aAddr0 + so;
        const uint32_t bB = bAddr0 + so;

        uint32_t af[2][4][4];
        uint32_t bf[2][4][2];

        {
            uint32_t t0[4], t1[4];
            LDSM4(t0, bB + chB[0]);
            LDSM4(t1, bB + 2048 + chB[0]);
            bf[0][0][0]=t0[0]; bf[0][0][1]=t0[2];
            bf[0][1][0]=t0[1]; bf[0][1][1]=t0[3];
            bf[0][2][0]=t1[0]; bf[0][2][1]=t1[2];
            bf[0][3][0]=t1[1]; bf[0][3][1]=t1[3];
            #pragma unroll
            for (int mt = 0; mt < 4; mt++)
                LDSM4(af[0][mt], aB + (uint32_t)(mt*2048) + chA[0]);
        }

        #pragma unroll
        for (int kk = 0; kk < 4; kk++) {
            const int cb = kk & 1;
            if (kk < 3) {
                uint32_t t0[4], t1[4];
                LDSM4(t0, bB + chB[kk+1]);
                LDSM4(t1, bB + 2048 + chB[kk+1]);
                bf[cb^1][0][0]=t0[0]; bf[cb^1][0][1]=t0[2];
                bf[cb^1][1][0]=t0[1]; bf[cb^1][1][1]=t0[3];
                bf[cb^1][2][0]=t1[0]; bf[cb^1][2][1]=t1[2];
                bf[cb^1][3][0]=t1[1]; bf[cb^1][3][1]=t1[3];
                #pragma unroll
                for (int mt = 0; mt < 4; mt++)
                    LDSM4(af[cb^1][mt], aB + (uint32_t)(mt*2048) + chA[kk+1]);
            }
            #pragma unroll
            for (int mt = 0; mt < 4; mt++)
                #pragma unroll
                for (int nt = 0; nt < 4; nt++)
                    MMA_FP16(c[mt][nt], af[cb][mt], bf[cb][nt]);
        }
    };

    const int NS = K / BK;
    issue_loads(0, 0);
    issue_loads(1, 1);

    for (int s = 0; s < NS; s++) {
        const int bi = s % NSTG;
        if (s + 1 < NS) asm volatile("cp.async.wait_group 1;\n" ::: "memory");
        else            asm volatile("cp.async.wait_group 0;\n" ::: "memory");
        __syncthreads();
        if (s + 2 < NS) issue_loads(s + 2, (s + 2) % NSTG);
        compute_stage(bi);
    }

    #pragma unroll
    for (int mt = 0; mt < 4; mt++) {
        #pragma unroll
        for (int nt = 0; nt < 4; nt++) {
            int row = bm + wm*64 + mt*16 + (lane >> 2);
            int col = bn + wn*32 + nt*8 + (lane & 3)*2;
            *reinterpret_cast<float2*>(C + (size_t)row*N + col) =
                make_float2(c[mt][nt][0], c[mt][nt][1]);
            *reinterpret_cast<float2*>(C + (size_t)(row+8)*N + col) =
                make_float2(c[mt][nt][2], c[mt][nt][3]);
        }
    }
}

// ============================================================================
// WKV parallel scan (single-exp forms, bit-identical to two-exp).
// ============================================================================

__global__ void wkv_chunk_kernel(const float* __restrict__ kk, const float* __restrict__ vv,
                                 const float* __restrict__ td)
{
    int g  = blockIdx.x * 256 + threadIdx.x;
    int d  = g & (D_-1);
    int ch = (g >> 11) & (NCH-1);
    int b  = g >> 16;
    float w = expf(td[d]);

    float alpha = 0.0f, beta = 0.0f, eps = -1e30f;
    size_t base = ((size_t)b * T_ + (size_t)ch * CL) * D_ + d;

    #pragma unroll 4
    for (int i = 0; i < CL; i++) {
        size_t idx = base + (size_t)i * D_;
        float kt = kk[idx];
        float vt = vv[idx];
        float ww2 = eps - w;
        float d2  = ww2 - kt;
        float e   = __expf(-fabsf(d2));
        float e1b = (d2 < 0.0f) ? e    : 1.0f;
        float e2b = (d2 < 0.0f) ? 1.0f : e;
        alpha = e1b*alpha + e2b*vt;
        beta  = e1b*beta + e2b;
        eps   = fmaxf(ww2, kt);
    }
    size_t o = ((size_t)b * NCH + ch) * D_ + d;
    g_agg[o]         = alpha;
    g_agg[BDN + o]   = beta;
    g_agg[2*BDN + o] = eps;
}

// stitch: loads batched 8 chunks ahead (MLP 24) before the dependent combine.
__global__ void wkv_stitch_kernel(const float* __restrict__ td)
{
    int g = blockIdx.x * 256 + threadIdx.x;
    int d = g & (D_-1);
    int b = g >> 11;
    float w  = expf(td[d]);
    float dl = -w * (float)CL;

    float a = 0.0f, bt = 0.0f, e = -1e30f;
    for (int c0 = 0; c0 < NCH; c0 += 8) {
        float pa[8], pb[8], pe[8];
        #pragma unroll
        for (int j = 0; j < 8; j++) {
            size_t o = ((size_t)b * NCH + c0 + j) * D_ + d;
            pa[j] = g_agg[o];
            pb[j] = g_agg[BDN + o];
            pe[j] = g_agg[2*BDN + o];
        }
        #pragma unroll
        for (int j = 0; j < 8; j++) {
            size_t o = ((size_t)b * NCH + c0 + j) * D_ + d;
            g_car[o]         = a;
            g_car[BDN + o]   = bt;
            g_car[2*BDN + o] = e;
            float ein = e + dl;
            float dd  = ein - pe[j];
            float ee  = __expf(-fabsf(dd));
            float f1  = (dd < 0.0f) ? ee   : 1.0f;
            float f2  = (dd < 0.0f) ? 1.0f : ee;
            a  = f1*a  + f2*pa[j];
            bt = f1*bt + f2*pb[j];
            e  = fmaxf(ein, pe[j]);
        }
    }
}

__global__ void wkv_apply_kernel(const float* __restrict__ kk, const float* __restrict__ vv,
                                 const float* __restrict__ rr,
                                 const float* __restrict__ td, const float* __restrict__ tf)
{
    int g  = blockIdx.x * 256 + threadIdx.x;
    int d  = g & (D_-1);
    int ch = (g >> 11) & (NCH-1);
    int b  = g >> 16;
    float w = expf(td[d]);
    float u = tf[d];

    size_t o = ((size_t)b * NCH + ch) * D_ + d;
    float alpha = g_car[o];
    float beta  = g_car[BDN + o];
    float eps   = g_car[2*BDN + o];

    size_t base = ((size_t)b * T_ + (size_t)ch * CL) * D_ + d;

    #pragma unroll 4
    for (int i = 0; i < CL; i++) {
        size_t idx = base + (size_t)i * D_;
        float kt = kk[idx];
        float vt = vv[idx];
        float rt = rr[idx];

        float ww = u + kt;
        float dd = eps - ww;
        float eo = __expf(-fabsf(dd));
        float e1 = (dd < 0.0f) ? eo   : 1.0f;
        float e2 = (dd < 0.0f) ? 1.0f : eo;
        float out = __fdividef(e1*alpha + e2*vt, e1*beta + e2);

        float ww2 = eps - w;
        float d2  = ww2 - kt;
        float eb  = __expf(-fabsf(d2));
        float e1b = (d2 < 0.0f) ? eb   : 1.0f;
        float e2b = (d2 < 0.0f) ? 1.0f : eb;
        alpha = e1b*alpha + e2b*vt;
        beta  = e1b*beta + e2b;
        eps   = fmaxf(ww2, kt);

        float sr = __fdividef(1.0f, 1.0f + __expf(-rt));
        g_uh[idx] = __float2half(out * sr);
    }
}

// ---------------- launch ----------------
extern "C" void kernel_launch(void* const* d_in, const int* in_sizes, int n_in,
                              void* d_out, int out_size)
{
    const float* x  = (const float*)d_in[0];
    const float* td = (const float*)d_in[1];
    const float* tf = (const float*)d_in[2];
    const float* mk = (const float*)d_in[3];
    const float* mv = (const float*)d_in[4];
    const float* mr = (const float*)d_in[5];
    const float* Wk = (const float*)d_in[6];
    const float* Wv = (const float*)d_in[7];
    const float* Wr = (const float*)d_in[8];
    const float* Wo = (const float*)d_in[9];
    float* out = (float*)d_out;

    __half *xh, *wh, *uh;
    float* kvr;
    cudaGetSymbolAddress((void**)&xh,  g_xh);
    cudaGetSymbolAddress((void**)&wh,  g_wh);
    cudaGetSymbolAddress((void**)&kvr, g_kvr);
    cudaGetSymbolAddress((void**)&uh,  g_uh);

    const int GEMM_SMEM = NSTG * STAGE_BYTES;  // 98304
    cudaFuncSetAttribute(gemm_kernel, cudaFuncAttributeMaxDynamicSharedMemorySize, GEMM_SMEM);

    prep_kernel<<<(unsigned)((MD + 255) / 256), 256>>>(x, mk, mv, mr, Wk, Wv, Wr, Wo);

    dim3 grid3(D_ / BN, M_ / BM, 3);   // fused k/v/r GEMMs
    gemm_kernel<<<grid3, 256, GEMM_SMEM>>>(xh, wh, kvr, M_, D_, D_,
                                           (int)MD, (int)DD);

    wkv_chunk_kernel<<<BDN/256, 256>>>(kvr, kvr + MD, td);
    wkv_stitch_kernel<<<(B_*D_)/256, 256>>>(td);
    wkv_apply_kernel<<<BDN/256, 256>>>(kvr, kvr + MD, kvr + 2*MD, td, tf);

    dim3 grid1(D_ / BN, M_ / BM, 1);
    gemm_kernel<<<grid1, 256, GEMM_SMEM>>>(uh, wh + 3*DD, out, M_, D_, D_, 0, 0);
}

// round 17
// speedup vs baseline: 1.0268x; 1.0034x over previous
#include <cuda_runtime.h>
#include <cuda_fp16.h>
#include <cstdint>

// ---------------- problem constants ----------------
#define D_ 2048
#define B_ 4
#define T_ 2048
#define M_ (B_*T_)          // 8192

#define MD ((size_t)M_*(size_t)D_)   // 16,777,216
#define DD ((size_t)D_*(size_t)D_)   //  4,194,304  (4*DD == MD)

#define NCH 32
#define CL  (T_/NCH)                 // 64
#define BDN (B_*NCH*D_)              // 262,144

// ---------------- scratch (static device globals — allocation-free) --------
__device__ __align__(256) __half g_xh[3*MD];    // mixed activations (fp16)
__device__ __align__(256) __half g_wh[4*DD];    // weights (fp16)
__device__ __align__(256) float  g_kvr[3*MD];   // k, v, r (fp32 GEMM outputs)
__device__ __align__(256) __half g_uh[MD];      // wkv*sigmoid(r) (fp16)
__device__ __align__(256) float  g_agg[3*BDN];  // chunk aggregates
__device__ __align__(256) float  g_car[3*BDN];  // chunk carry-ins

// ---------------- fused prep: weight->fp16 AND time-shift mix ----------------
__global__ void prep_kernel(const float* __restrict__ x,
                            const float* __restrict__ mk,
                            const float* __restrict__ mv,
                            const float* __restrict__ mr,
                            const float* __restrict__ W0, const float* __restrict__ W1,
                            const float* __restrict__ W2, const float* __restrict__ W3)
{
    size_t i = (size_t)blockIdx.x * blockDim.x + threadIdx.x;
    if (i >= MD) return;

    size_t which = i / DD;
    const float* Ws = (which == 0) ? W0 : (which == 1) ? W1 : (which == 2) ? W2 : W3;
    g_wh[i] = __float2half(Ws[i - which*DD]);

    int d = (int)(i & (size_t)(D_-1));
    int t = (int)((i / D_) & (size_t)(T_-1));
    float xv = x[i];
    float lx = (t > 0) ? x[i - D_] : 0.0f;
    float dx = xv - lx;

    g_xh[i]        = __float2half(fmaf(dx, mk[d], lx));
    g_xh[MD + i]   = __float2half(fmaf(dx, mv[d], lx));
    g_xh[2*MD + i] = __float2half(fmaf(dx, mr[d], lx));
}

// ---------------- fp16 single-pass GEMM ----------------
// BK=32, NSTG=5 ring, commit 3 stages ahead (wait_group 2 keeps 2-stage load
// slack). Fragments pipelined ACROSS stage barriers: a warp enters each stage
// with its kk=0 fragments already in registers, eliminating the post-barrier
// LDSM convoy.
#define BM 128
#define BN 128
#define BK 32
#define NSTG 5
#define TILE_BYTES (BM*BK*2)         // 8192
#define STAGE_BYTES (2*TILE_BYTES)   // 16384

__device__ __forceinline__ uint32_t cvta_s(const void* p) {
    return (uint32_t)__cvta_generic_to_shared(p);
}
__device__ __forceinline__ void cp16(uint32_t s, const void* g) {
    asm volatile("cp.async.cg.shared.global [%0], [%1], 16;\n" :: "r"(s), "l"(g));
}

#define MMA_FP16(cc, aa, bb)                                                    \
    asm volatile("mma.sync.aligned.m16n8k16.row.col.f32.f16.f16.f32 "            \
                 "{%0,%1,%2,%3},{%4,%5,%6,%7},{%8,%9},{%0,%1,%2,%3};\n"          \
                 : "+f"(cc[0]), "+f"(cc[1]), "+f"(cc[2]), "+f"(cc[3])            \
                 : "r"(aa[0]), "r"(aa[1]), "r"(aa[2]), "r"(aa[3]),               \
                   "r"(bb[0]), "r"(bb[1]))

#define LDSM4(dst, ad)                                                           \
    asm volatile("ldmatrix.sync.aligned.m8n8.x4.shared.b16 {%0,%1,%2,%3},[%4];\n"\
                 : "=r"((dst)[0]), "=r"((dst)[1]), "=r"((dst)[2]), "=r"((dst)[3])\
                 : "r"(ad))

__global__ void __launch_bounds__(256, 2)
gemm_kernel(const __half* __restrict__ Abase, const __half* __restrict__ Bbase,
            float* __restrict__ Cbase, int M, int N, int K,
            int strideAz, int strideBz)
{
    extern __shared__ __align__(16) char smem_raw[];
    const uint32_t sbase = cvta_s(smem_raw);

    const int tid  = threadIdx.x;
    const int lane = tid & 31;
    const int warp = tid >> 5;
    const int wm   = warp >> 2;
    const int wn   = warp & 3;

    const int z  = blockIdx.z;
    const __half* Ah = Abase + (size_t)z * (size_t)strideAz;
    const __half* Bh = Bbase + (size_t)z * (size_t)strideBz;
    float*        C  = Cbase + (size_t)z * (size_t)strideAz;

    const int bm = blockIdx.y * BM;
    const int bn = blockIdx.x * BN;

    float c[4][4][4];
    #pragma unroll
    for (int i = 0; i < 4; i++)
        #pragma unroll
        for (int j = 0; j < 4; j++)
            #pragma unroll
            for (int q = 0; q < 4; q++) c[i][j][q] = 0.0f;

    const __half* gbase[2] = { Ah + (size_t)bm*K, Bh + (size_t)bn*K };

    // ldmatrix addressing: tiles are [128 rows][32 cols] fp16, 64B rows,
    // swizzle: byte = r*64 + ((c ^ ((r>>1)&3)) << 4), chunk c in 0..3.
    const int rA = wm*64 + (lane & 15);
    const int rB = wn*32 + (lane & 15);
    const int hi = lane >> 4;
    const uint32_t aRow = (uint32_t)(rA*64);
    const uint32_t bRow = (uint32_t)(TILE_BYTES + rB*64);
    uint32_t chA[2], chB[2];
    #pragma unroll
    for (int kk = 0; kk < 2; kk++) {
        chA[kk] = (uint32_t)(((kk*2 + hi) ^ ((rA >> 1) & 3)) << 4);
        chB[kk] = (uint32_t)(((kk*2 + hi) ^ ((rB >> 1) & 3)) << 4);
    }

    auto issue_loads = [&](int s, int bi) {
        const int k0 = s * BK;
        const uint32_t st = sbase + (uint32_t)bi * STAGE_BYTES;
        #pragma unroll
        for (int q = 0; q < 4; q++) {
            int cid = tid + q*256;              // 1024 16B-chunks per stage
            int op  = cid >> 9;                 // 0..1
            int wi  = cid & 511;
            int rr  = wi >> 2, cc = wi & 3;
            cp16(st + (uint32_t)op*TILE_BYTES
                    + (uint32_t)(rr*64 + ((cc ^ ((rr >> 1) & 3)) << 4)),
                 gbase[op] + (size_t)rr*K + k0 + cc*8);
        }
        asm volatile("cp.async.commit_group;\n");
    };

    uint32_t af[2][4][4];    // [buf][mt][4]
    uint32_t bf[2][4][2];    // [buf][nt][2]

    auto preB = [&](int buf, uint32_t bB, uint32_t ch) {
        uint32_t t0[4], t1[4];
        LDSM4(t0, bB + ch);
        LDSM4(t1, bB + 1024 + ch);
        bf[buf][0][0]=t0[0]; bf[buf][0][1]=t0[2];
        bf[buf][1][0]=t0[1]; bf[buf][1][1]=t0[3];
        bf[buf][2][0]=t1[0]; bf[buf][2][1]=t1[2];
        bf[buf][3][0]=t1[1]; bf[buf][3][1]=t1[3];
    };
    auto preA = [&](int buf, uint32_t aB, uint32_t ch) {
        #pragma unroll
        for (int mt = 0; mt < 4; mt++)
            LDSM4(af[buf][mt], aB + (uint32_t)(mt*1024) + ch);
    };

    // prologue: 3 stages in flight; preload stage-0 kk=0 fragments
    issue_loads(0, 0);
    issue_loads(1, 1);
    issue_loads(2, 2);
    asm volatile("cp.async.wait_group 2;\n" ::: "memory");   // G0 retired
    __syncthreads();
    preB(0, sbase + bRow, chB[0]);
    preA(0, sbase + aRow, chA[0]);

    const int NS = K / BK;                     // 64 stages
    for (int s = 0; s < NS; s++) {
        const int bi = s % NSTG;
        if (s + 3 < NS) issue_loads(s + 3, (s + 3) % NSTG);
        // retire G_{s+1} (keep up to 2 newer groups in flight)
        if (s + 3 < NS)       asm volatile("cp.async.wait_group 2;\n" ::: "memory");
        else if (s + 3 == NS) asm volatile("cp.async.wait_group 1;\n" ::: "memory");
        else                  asm volatile("cp.async.wait_group 0;\n" ::: "memory");
        __syncthreads();

        const uint32_t sb  = sbase + (uint32_t)bi * STAGE_BYTES;
        const uint32_t nsb = sbase + (uint32_t)((s + 1) % NSTG) * STAGE_BYTES;

        // kk=0: prefetch this stage's kk=1 frags; MMA with buf0 (preloaded)
        preB(1, sb + bRow, chB[1]);
        preA(1, sb + aRow, chA[1]);
        #pragma unroll
        for (int mt = 0; mt < 4; mt++)
            #pragma unroll
            for (int nt = 0; nt < 4; nt++)
                MMA_FP16(c[mt][nt], af[0][mt], bf[0][nt]);

        // kk=1: prefetch NEXT stage's kk=0 frags (pre-barrier); MMA with buf1
        if (s + 1 < NS) {
            preB(0, nsb + bRow, chB[0]);
            preA(0, nsb + aRow, chA[0]);
        }
        #pragma unroll
        for (int mt = 0; mt < 4; mt++)
            #pragma unroll
            for (int nt = 0; nt < 4; nt++)
                MMA_FP16(c[mt][nt], af[1][mt], bf[1][nt]);
    }

    // epilogue
    #pragma unroll
    for (int mt = 0; mt < 4; mt++) {
        #pragma unroll
        for (int nt = 0; nt < 4; nt++) {
            int row = bm + wm*64 + mt*16 + (lane >> 2);
            int col = bn + wn*32 + nt*8 + (lane & 3)*2;
            *reinterpret_cast<float2*>(C + (size_t)row*N + col) =
                make_float2(c[mt][nt][0], c[mt][nt][1]);
            *reinterpret_cast<float2*>(C + (size_t)(row+8)*N + col) =
                make_float2(c[mt][nt][2], c[mt][nt][3]);
        }
    }
}

// ============================================================================
// WKV parallel scan (single-exp forms, bit-identical to two-exp).
// ============================================================================

__global__ void wkv_chunk_kernel(const float* __restrict__ kk, const float* __restrict__ vv,
                                 const float* __restrict__ td)
{
    int g  = blockIdx.x * 256 + threadIdx.x;
    int d  = g & (D_-1);
    int ch = (g >> 11) & (NCH-1);
    int b  = g >> 16;
    float w = expf(td[d]);

    float alpha = 0.0f, beta = 0.0f, eps = -1e30f;
    size_t base = ((size_t)b * T_ + (size_t)ch * CL) * D_ + d;

    #pragma unroll 4
    for (int i = 0; i < CL; i++) {
        size_t idx = base + (size_t)i * D_;
        float kt = kk[idx];
        float vt = vv[idx];
        float ww2 = eps - w;
        float d2  = ww2 - kt;
        float e   = __expf(-fabsf(d2));
        float e1b = (d2 < 0.0f) ? e    : 1.0f;
        float e2b = (d2 < 0.0f) ? 1.0f : e;
        alpha = e1b*alpha + e2b*vt;
        beta  = e1b*beta + e2b;
        eps   = fmaxf(ww2, kt);
    }
    size_t o = ((size_t)b * NCH + ch) * D_ + d;
    g_agg[o]         = alpha;
    g_agg[BDN + o]   = beta;
    g_agg[2*BDN + o] = eps;
}

// stitch: loads batched 8 chunks ahead (MLP 24) before the dependent combine.
__global__ void wkv_stitch_kernel(const float* __restrict__ td)
{
    int g = blockIdx.x * 256 + threadIdx.x;
    int d = g & (D_-1);
    int b = g >> 11;
    float w  = expf(td[d]);
    float dl = -w * (float)CL;

    float a = 0.0f, bt = 0.0f, e = -1e30f;
    for (int c0 = 0; c0 < NCH; c0 += 8) {
        float pa[8], pb[8], pe[8];
        #pragma unroll
        for (int j = 0; j < 8; j++) {
            size_t o = ((size_t)b * NCH + c0 + j) * D_ + d;
            pa[j] = g_agg[o];
            pb[j] = g_agg[BDN + o];
            pe[j] = g_agg[2*BDN + o];
        }
        #pragma unroll
        for (int j = 0; j < 8; j++) {
            size_t o = ((size_t)b * NCH + c0 + j) * D_ + d;
            g_car[o]         = a;
            g_car[BDN + o]   = bt;
            g_car[2*BDN + o] = e;
            float ein = e + dl;
            float dd  = ein - pe[j];
            float ee  = __expf(-fabsf(dd));
            float f1  = (dd < 0.0f) ? ee   : 1.0f;
            float f2  = (dd < 0.0f) ? 1.0f : ee;
            a  = f1*a  + f2*pa[j];
            bt = f1*bt + f2*pb[j];
            e  = fmaxf(ein, pe[j]);
        }
    }
}

__global__ void wkv_apply_kernel(const float* __restrict__ kk, const float* __restrict__ vv,
                                 const float* __restrict__ rr,
                                 const float* __restrict__ td, const float* __restrict__ tf)
{
    int g  = blockIdx.x * 256 + threadIdx.x;
    int d  = g & (D_-1);
    int ch = (g >> 11) & (NCH-1);
    int b  = g >> 16;
    float w = expf(td[d]);
    float u = tf[d];

    size_t o = ((size_t)b * NCH + ch) * D_ + d;
    float alpha = g_car[o];
    float beta  = g_car[BDN + o];
    float eps   = g_car[2*BDN + o];

    size_t base = ((size_t)b * T_ + (size_t)ch * CL) * D_ + d;

    #pragma unroll 4
    for (int i = 0; i < CL; i++) {
        size_t idx = base + (size_t)i * D_;
        float kt = kk[idx];
        float vt = vv[idx];
        float rt = rr[idx];

        float ww = u + kt;
        float dd = eps - ww;
        float eo = __expf(-fabsf(dd));
        float e1 = (dd < 0.0f) ? eo   : 1.0f;
        float e2 = (dd < 0.0f) ? 1.0f : eo;
        float out = __fdividef(e1*alpha + e2*vt, e1*beta + e2);

        float ww2 = eps - w;
        float d2  = ww2 - kt;
        float eb  = __expf(-fabsf(d2));
        float e1b = (d2 < 0.0f) ? eb   : 1.0f;
        float e2b = (d2 < 0.0f) ? 1.0f : eb;
        alpha = e1b*alpha + e2b*vt;
        beta  = e1b*beta + e2b;
        eps   = fmaxf(ww2, kt);

        float sr = __fdividef(1.0f, 1.0f + __expf(-rt));
        g_uh[idx] = __float2half(out * sr);
    }
}

// ---------------- launch ----------------
extern "C" void kernel_launch(void* const* d_in, const int* in_sizes, int n_in,
                              void* d_out, int out_size)
{
    const float* x  = (const float*)d_in[0];
    const float* td = (const float*)d_in[1];
    const float* tf = (const float*)d_in[2];
    const float* mk = (const float*)d_in[3];
    const float* mv = (const float*)d_in[4];
    const float* mr = (const float*)d_in[5];
    const float* Wk = (const float*)d_in[6];
    const float* Wv = (const float*)d_in[7];
    const float* Wr = (const float*)d_in[8];
    const float* Wo = (const float*)d_in[9];
    float* out = (float*)d_out;

    __half *xh, *wh, *uh;
    float* kvr;
    cudaGetSymbolAddress((void**)&xh,  g_xh);
    cudaGetSymbolAddress((void**)&wh,  g_wh);
    cudaGetSymbolAddress((void**)&kvr, g_kvr);
    cudaGetSymbolAddress((void**)&uh,  g_uh);

    const int GEMM_SMEM = NSTG * STAGE_BYTES;  // 81920
    cudaFuncSetAttribute(gemm_kernel, cudaFuncAttributeMaxDynamicSharedMemorySize, GEMM_SMEM);

    prep_kernel<<<(unsigned)((MD + 255) / 256), 256>>>(x, mk, mv, mr, Wk, Wv, Wr, Wo);

    dim3 grid3(D_ / BN, M_ / BM, 3);   // fused k/v/r GEMMs
    gemm_kernel<<<grid3, 256, GEMM_SMEM>>>(xh, wh, kvr, M_, D_, D_,
                                           (int)MD, (int)DD);

    wkv_chunk_kernel<<<BDN/256, 256>>>(kvr, kvr + MD, td);
    wkv_stitch_kernel<<<(B_*D_)/256, 256>>>(td);
    wkv_apply_kernel<<<BDN/256, 256>>>(kvr, kvr + MD, kvr + 2*MD, td, tf);

    dim3 grid1(D_ / BN, M_ / BM, 1);
    gemm_kernel<<<grid1, 256, GEMM_SMEM>>>(uh, wh + 3*DD, out, M_, D_, D_, 0, 0);
}